// round 1
// baseline (speedup 1.0000x reference)
#include <cuda_runtime.h>
#include <cuda_bf16.h>
#include <cstdint>

#define B_SZ 4096
#define D_SZ 1024
#define EPS_F 1e-7f

// Scratch (allocation-free rule: __device__ globals)
__device__ __nv_bfloat16 g_ln[B_SZ * D_SZ];
__device__ __nv_bfloat16 g_rn[B_SZ * D_SZ];
__device__ float g_rowsum[B_SZ];
__device__ float g_colsum[B_SZ];
__device__ float g_diag[B_SZ];

// ---------------------------------------------------------------------------
// Fast exp on FMA pipe (avoids MUFU bottleneck). Valid for x > -80.
// exp(x) = 2^(x*log2e); n = round(y) via magic add; 2^f by degree-5 Taylor.
// ---------------------------------------------------------------------------
__device__ __forceinline__ float fast_exp(float x) {
    float y = x * 1.4426950408889634f;
    float t = y + 12582912.0f;                    // 1.5 * 2^23 magic
    int   n = __float_as_int(t) - 0x4B400000;
    float f = y - (t - 12582912.0f);              // f in [-0.5, 0.5]
    float p = 1.3333558e-3f;
    p = fmaf(p, f, 9.6181291e-3f);
    p = fmaf(p, f, 5.5504109e-2f);
    p = fmaf(p, f, 2.4022651e-1f);
    p = fmaf(p, f, 6.9314718e-1f);
    p = fmaf(p, f, 1.0f);
    return p * __int_as_float((n + 127) << 23);
}

// ---------------------------------------------------------------------------
// Kernel 1: l2-normalize rows of left/right -> bf16; zero stat arrays.
// grid = 2*B_SZ blocks of 256 threads; one row per block (1024 f32 per row).
// ---------------------------------------------------------------------------
__global__ void normalize_kernel(const float* __restrict__ left,
                                 const float* __restrict__ right) {
    int row = blockIdx.x;
    const float* src;
    __nv_bfloat16* dst;
    if (row < B_SZ) {
        src = left + (size_t)row * D_SZ;
        dst = g_ln + (size_t)row * D_SZ;
    } else {
        int r = row - B_SZ;
        src = right + (size_t)r * D_SZ;
        dst = g_rn + (size_t)r * D_SZ;
    }
    int tid = threadIdx.x;
    float4 v = ((const float4*)src)[tid];
    float ss = v.x * v.x + v.y * v.y + v.z * v.z + v.w * v.w;
    #pragma unroll
    for (int o = 16; o > 0; o >>= 1) ss += __shfl_xor_sync(0xffffffffu, ss, o);
    __shared__ float warpsum[8];
    if ((tid & 31) == 0) warpsum[tid >> 5] = ss;
    __syncthreads();
    float tot = warpsum[0] + warpsum[1] + warpsum[2] + warpsum[3]
              + warpsum[4] + warpsum[5] + warpsum[6] + warpsum[7];
    float inv = rsqrtf(fmaxf(tot, EPS_F));
    __nv_bfloat162 h0 = __floats2bfloat162_rn(v.x * inv, v.y * inv);
    __nv_bfloat162 h1 = __floats2bfloat162_rn(v.z * inv, v.w * inv);
    uint2 pack;
    pack.x = *(const unsigned int*)&h0;
    pack.y = *(const unsigned int*)&h1;
    ((uint2*)dst)[tid] = pack;
    if (tid == 0 && row < B_SZ) {
        g_rowsum[row] = 0.0f;
        g_colsum[row] = 0.0f;
    }
}

// ---------------------------------------------------------------------------
// Kernel 2: tiled bf16 GEMM S = LN * RN^T (128x128 per block, K-step 64),
// epilogue: e = exp(scale*s - scale), accumulate row sums / col sums via
// atomics, write diagonal exp values.
// ---------------------------------------------------------------------------
#define BM 128
#define BN 128
#define BK 64
#define LDSB 72  // padded stride in halves -> conflict-free fragment loads

__device__ __forceinline__ void mma16816(float d[4], const uint32_t a[4],
                                         const uint32_t b[2]) {
    asm volatile(
        "mma.sync.aligned.m16n8k16.row.col.f32.bf16.bf16.f32 "
        "{%0,%1,%2,%3}, {%4,%5,%6,%7}, {%8,%9}, {%0,%1,%2,%3};\n"
        : "+f"(d[0]), "+f"(d[1]), "+f"(d[2]), "+f"(d[3])
        : "r"(a[0]), "r"(a[1]), "r"(a[2]), "r"(a[3]), "r"(b[0]), "r"(b[1]));
}

__global__ __launch_bounds__(256)
void gemm_stats_kernel(const float* __restrict__ temperature) {
    __shared__ __nv_bfloat16 As[BM][LDSB];
    __shared__ __nv_bfloat16 Bs[BN][LDSB];

    const int bi = blockIdx.y;
    const int bj = blockIdx.x;
    const int tid = threadIdx.x;
    const int warp = tid >> 5;
    const int lane = tid & 31;
    const int wr = warp >> 2;   // 0..1  (64-row slabs)
    const int wc = warp & 3;    // 0..3  (32-col slabs)
    const int grp = lane >> 2;  // 0..7
    const int qid = lane & 3;   // 0..3

    float acc[4][4][4];
    #pragma unroll
    for (int mt = 0; mt < 4; ++mt)
        #pragma unroll
        for (int nt = 0; nt < 4; ++nt)
            #pragma unroll
            for (int c = 0; c < 4; ++c) acc[mt][nt][c] = 0.0f;

    const __nv_bfloat16* Ag = g_ln + (size_t)(bi * BM) * D_SZ;
    const __nv_bfloat16* Bg = g_rn + (size_t)(bj * BN) * D_SZ;

    const int ldr = tid >> 3;        // 0..31
    const int ldc = (tid & 7) * 8;   // 0..56 step 8

    for (int k0 = 0; k0 < D_SZ; k0 += BK) {
        #pragma unroll
        for (int p = 0; p < 4; ++p) {
            int r = ldr + p * 32;
            *(float4*)&As[r][ldc] =
                *(const float4*)&Ag[(size_t)r * D_SZ + k0 + ldc];
            *(float4*)&Bs[r][ldc] =
                *(const float4*)&Bg[(size_t)r * D_SZ + k0 + ldc];
        }
        __syncthreads();
        #pragma unroll
        for (int kk = 0; kk < BK; kk += 16) {
            uint32_t af[4][4], bf[4][2];
            #pragma unroll
            for (int mt = 0; mt < 4; ++mt) {
                int r = wr * 64 + mt * 16 + grp;
                af[mt][0] = *(const uint32_t*)&As[r][kk + 2 * qid];
                af[mt][1] = *(const uint32_t*)&As[r + 8][kk + 2 * qid];
                af[mt][2] = *(const uint32_t*)&As[r][kk + 2 * qid + 8];
                af[mt][3] = *(const uint32_t*)&As[r + 8][kk + 2 * qid + 8];
            }
            #pragma unroll
            for (int nt = 0; nt < 4; ++nt) {
                int c = wc * 32 + nt * 8 + grp;
                bf[nt][0] = *(const uint32_t*)&Bs[c][kk + 2 * qid];
                bf[nt][1] = *(const uint32_t*)&Bs[c][kk + 2 * qid + 8];
            }
            #pragma unroll
            for (int mt = 0; mt < 4; ++mt)
                #pragma unroll
                for (int nt = 0; nt < 4; ++nt)
                    mma16816(acc[mt][nt], af[mt], bf[nt]);
        }
        __syncthreads();
    }

    // ---- epilogue ----
    const float scale = __expf(temperature[0]);
    const float shift = scale;  // |dot| <= 1 -> exponent in [-2*scale, 0]

    #pragma unroll
    for (int mt = 0; mt < 4; ++mt)
        #pragma unroll
        for (int nt = 0; nt < 4; ++nt)
            #pragma unroll
            for (int c = 0; c < 4; ++c)
                acc[mt][nt][c] = fast_exp(fmaf(acc[mt][nt][c], scale, -shift));

    // row sums: reduce over qid (lanes sharing a row), then atomics
    #pragma unroll
    for (int mt = 0; mt < 4; ++mt) {
        float s0 = 0.0f, s1 = 0.0f;
        #pragma unroll
        for (int nt = 0; nt < 4; ++nt) {
            s0 += acc[mt][nt][0] + acc[mt][nt][1];
            s1 += acc[mt][nt][2] + acc[mt][nt][3];
        }
        s0 += __shfl_xor_sync(0xffffffffu, s0, 1);
        s0 += __shfl_xor_sync(0xffffffffu, s0, 2);
        s1 += __shfl_xor_sync(0xffffffffu, s1, 1);
        s1 += __shfl_xor_sync(0xffffffffu, s1, 2);
        if (qid == 0) {
            int row = bi * BM + wr * 64 + mt * 16 + grp;
            atomicAdd(&g_rowsum[row], s0);
            atomicAdd(&g_rowsum[row + 8], s1);
        }
    }

    // col sums: reduce over grp (lanes sharing a column), then atomics
    #pragma unroll
    for (int nt = 0; nt < 4; ++nt) {
        float t0 = 0.0f, t1 = 0.0f;
        #pragma unroll
        for (int mt = 0; mt < 4; ++mt) {
            t0 += acc[mt][nt][0] + acc[mt][nt][2];
            t1 += acc[mt][nt][1] + acc[mt][nt][3];
        }
        t0 += __shfl_xor_sync(0xffffffffu, t0, 4);
        t0 += __shfl_xor_sync(0xffffffffu, t0, 8);
        t0 += __shfl_xor_sync(0xffffffffu, t0, 16);
        t1 += __shfl_xor_sync(0xffffffffu, t1, 4);
        t1 += __shfl_xor_sync(0xffffffffu, t1, 8);
        t1 += __shfl_xor_sync(0xffffffffu, t1, 16);
        if (grp == 0) {
            int col = bj * BN + wc * 32 + nt * 8 + 2 * qid;
            atomicAdd(&g_colsum[col], t0);
            atomicAdd(&g_colsum[col + 1], t1);
        }
    }

    // diagonal exp values (block on the diagonal only; unique writer each)
    if (bi == bj) {
        #pragma unroll
        for (int mt = 0; mt < 4; ++mt) {
            int lr = wr * 64 + mt * 16 + grp;
            #pragma unroll
            for (int nt = 0; nt < 4; ++nt) {
                int lc = wc * 32 + nt * 8 + 2 * qid;
                if (lr == lc)     g_diag[bi * BM + lr]     = acc[mt][nt][0];
                if (lr == lc + 1) g_diag[bi * BM + lr]     = acc[mt][nt][1];
                if (lr + 8 == lc)     g_diag[bi * BM + lr + 8] = acc[mt][nt][2];
                if (lr + 8 == lc + 1) g_diag[bi * BM + lr + 8] = acc[mt][nt][3];
            }
        }
    }
}

// ---------------------------------------------------------------------------
// Kernel 3: traces -> closed-form loss
// ---------------------------------------------------------------------------
__global__ void finalize_kernel(float* __restrict__ out) {
    int tid = threadIdx.x;
    float tl = 0.0f, tr = 0.0f;
    for (int i = tid; i < B_SZ; i += 256) {
        float d = g_diag[i];
        tl += d / g_rowsum[i];
        tr += d / g_colsum[i];
    }
    #pragma unroll
    for (int o = 16; o > 0; o >>= 1) {
        tl += __shfl_xor_sync(0xffffffffu, tl, o);
        tr += __shfl_xor_sync(0xffffffffu, tr, o);
    }
    __shared__ float sl[8], sr[8];
    if ((tid & 31) == 0) { sl[tid >> 5] = tl; sr[tid >> 5] = tr; }
    __syncthreads();
    if (tid == 0) {
        float TL = 0.0f, TR = 0.0f;
        #pragma unroll
        for (int w = 0; w < 8; ++w) { TL += sl[w]; TR += sr[w]; }
        float logeps = logf(EPS_F);          // log(1e-7)
        float log1m  = logf(1.0f - EPS_F);   // log(1-1e-7)
        float ll = -(TL * log1m + ((float)B_SZ - TL) * logeps);
        float lr = -(TR * log1m + ((float)B_SZ - TR) * logeps);
        out[0] = (ll + lr) * 0.5f / (float)B_SZ;
    }
}

// ---------------------------------------------------------------------------
extern "C" void kernel_launch(void* const* d_in, const int* in_sizes, int n_in,
                              void* d_out, int out_size) {
    const float* left  = (const float*)d_in[0];
    const float* right = (const float*)d_in[1];
    const float* temp  = (const float*)d_in[2];

    normalize_kernel<<<2 * B_SZ, 256>>>(left, right);
    dim3 grid(B_SZ / BN, B_SZ / BM);
    gemm_stats_kernel<<<grid, 256>>>(temp);
    finalize_kernel<<<1, 256>>>((float*)d_out);
}

// round 3
// speedup vs baseline: 1.2154x; 1.2154x over previous
#include <cuda_runtime.h>
#include <cuda_bf16.h>
#include <cstdint>

#define B_SZ 4096
#define D_SZ 1024
#define EPS_F 1e-7f

#define BK 64
#define BM 128
#define BN 256
#define NKB (D_SZ / BK)                 // 16 k-blocks
#define A_TILE_B (BM * 128)             // 16384 B  (128 rows x 128B)
#define B_TILE_B (BN * 128)             // 32768 B  (256 rows x 128B)
#define STAGE_B  (A_TILE_B + B_TILE_B)  // 49152 B
#define NSTAGE 3
#define SM_CTRL (NSTAGE * STAGE_B)      // 147456
#define DSMEM_TOTAL (SM_CTRL + 64)

#define SWZ(x) ((x) ^ (((x) >> 3) & 0x70))

// ---- scratch (allocation-free rule: __device__ globals) -------------------
// g_ln: tiled SW128 layout [rb(32)][kb(16)] -> contiguous 16KB A tiles
// g_rn: tiled SW128 layout [rb(16)][kb(16)] -> contiguous 32KB B tiles
__device__ __align__(1024) __nv_bfloat16 g_ln[B_SZ * D_SZ];
__device__ __align__(1024) __nv_bfloat16 g_rn[B_SZ * D_SZ];
__device__ float g_rowsum[B_SZ];
__device__ float g_colsum[B_SZ];
__device__ float g_diag[B_SZ];

// ---------------------------------------------------------------------------
__device__ __forceinline__ uint32_t smem_u32(const void* p) {
    uint32_t a;
    asm("{ .reg .u64 t; cvta.to.shared.u64 t, %1; cvt.u32.u64 %0, t; }"
        : "=r"(a) : "l"(p));
    return a;
}

__device__ __forceinline__ float fast_exp(float x) {
    float y = x * 1.4426950408889634f;
    float t = y + 12582912.0f;
    int   n = __float_as_int(t) - 0x4B400000;
    float f = y - (t - 12582912.0f);
    float p = 1.3333558e-3f;
    p = fmaf(p, f, 9.6181291e-3f);
    p = fmaf(p, f, 5.5504109e-2f);
    p = fmaf(p, f, 2.4022651e-1f);
    p = fmaf(p, f, 6.9314718e-1f);
    p = fmaf(p, f, 1.0f);
    return p * __int_as_float((n + 127) << 23);
}

// ---- mbarrier / bulk-copy helpers (plain sm_90 PTX, no 'a' features) ------
__device__ __forceinline__ void mb_init(uint32_t a, uint32_t cnt) {
    asm volatile("mbarrier.init.shared.b64 [%0], %1;" :: "r"(a), "r"(cnt) : "memory");
}
__device__ __forceinline__ void mb_expect(uint32_t a, uint32_t bytes) {
    asm volatile("mbarrier.arrive.expect_tx.shared.b64 _, [%0], %1;"
                 :: "r"(a), "r"(bytes) : "memory");
}
__device__ __forceinline__ void mb_wait(uint32_t a, uint32_t parity) {
    asm volatile(
        "{\n\t.reg .pred P;\n\t"
        "WL_%=:\n\t"
        "mbarrier.try_wait.parity.acquire.cta.shared::cta.b64 P, [%0], %1, 0x989680;\n\t"
        "@P bra.uni WD_%=;\n\t"
        "bra.uni WL_%=;\n\t"
        "WD_%=:\n\t}"
        :: "r"(a), "r"(parity) : "memory");
}
__device__ __forceinline__ void bulk_g2s(uint32_t dst, const void* src,
                                         uint32_t bytes, uint32_t mbar) {
    asm volatile(
        "cp.async.bulk.shared::cluster.global.mbarrier::complete_tx::bytes "
        "[%0], [%1], %2, [%3];"
        :: "r"(dst), "l"(src), "r"(bytes), "r"(mbar) : "memory");
}

// ---- mma / ldmatrix -------------------------------------------------------
__device__ __forceinline__ void mma16816(float d[4], const uint32_t a[4],
                                         const uint32_t b[2]) {
    asm volatile(
        "mma.sync.aligned.m16n8k16.row.col.f32.bf16.bf16.f32 "
        "{%0,%1,%2,%3}, {%4,%5,%6,%7}, {%8,%9}, {%0,%1,%2,%3};\n"
        : "+f"(d[0]), "+f"(d[1]), "+f"(d[2]), "+f"(d[3])
        : "r"(a[0]), "r"(a[1]), "r"(a[2]), "r"(a[3]), "r"(b[0]), "r"(b[1]));
}
__device__ __forceinline__ void ldsm_x4(uint32_t& r0, uint32_t& r1,
                                        uint32_t& r2, uint32_t& r3,
                                        uint32_t addr) {
    asm volatile("ldmatrix.sync.aligned.m8n8.x4.shared.b16 {%0,%1,%2,%3}, [%4];"
                 : "=r"(r0), "=r"(r1), "=r"(r2), "=r"(r3) : "r"(addr));
}

// swizzled byte offset inside a tile: row stride 128B, kb in [0,128)
__device__ __forceinline__ uint32_t swz_off(int row, int kb) {
    return (uint32_t)(row * 128 + (kb ^ ((row * 16) & 0x70)));
}

// ---------------------------------------------------------------------------
// Kernel 1: l2-normalize rows -> bf16 in SW128-swizzled tile layout.
// warp-per-row: grid 1024 x 256 threads (8 warps = 8 rows per block).
// ---------------------------------------------------------------------------
__global__ void normalize_kernel(const float* __restrict__ left,
                                 const float* __restrict__ right) {
    int warp = threadIdx.x >> 5, lane = threadIdx.x & 31;
    int row = blockIdx.x * 8 + warp;          // 0..8191
    bool isL = row < B_SZ;
    int r = isL ? row : row - B_SZ;
    const float* src = (isL ? left : right) + (size_t)r * D_SZ;

    float4 v[8];
    float ss = 0.0f;
    #pragma unroll
    for (int i = 0; i < 8; ++i) {
        v[i] = ((const float4*)src)[lane + 32 * i];
        ss += v[i].x * v[i].x + v[i].y * v[i].y + v[i].z * v[i].z + v[i].w * v[i].w;
    }
    #pragma unroll
    for (int o = 16; o > 0; o >>= 1) ss += __shfl_xor_sync(0xffffffffu, ss, o);
    float inv = rsqrtf(fmaxf(ss, EPS_F));

    char* base;
    int rr;
    if (isL) {
        base = (char*)g_ln + (size_t)(r >> 7) * NKB * A_TILE_B;
        rr = r & 127;
    } else {
        base = (char*)g_rn + (size_t)(r >> 8) * NKB * B_TILE_B;
        rr = r & 255;
    }
    size_t tile_b = isL ? A_TILE_B : B_TILE_B;

    #pragma unroll
    for (int i = 0; i < 8; ++i) {
        __nv_bfloat162 h0 = __floats2bfloat162_rn(v[i].x * inv, v[i].y * inv);
        __nv_bfloat162 h1 = __floats2bfloat162_rn(v[i].z * inv, v[i].w * inv);
        uint2 pack;
        pack.x = *(const unsigned int*)&h0;
        pack.y = *(const unsigned int*)&h1;
        int f = lane + 32 * i;                // float4 index in row, 0..255
        int kb = f >> 4;                      // k-block 0..15
        int kc = (f & 15) * 8;                // byte offset in [0,128), 8B units
        uint32_t off = (uint32_t)(rr * 128 + (kc ^ ((rr * 16) & 0x70)));
        *(uint2*)(base + (size_t)kb * tile_b + off) = pack;
    }
    if (lane == 0 && isL) { g_rowsum[r] = 0.0f; g_colsum[r] = 0.0f; }
}

// ---------------------------------------------------------------------------
// Kernel 2: bf16 mma.sync GEMM, 128x256 CTA tile, 512 threads (warp grid 2x8),
// cp.async.bulk 3-stage pipeline, ldmatrix fragment loads, fused exp /
// rowsum / colsum / diag epilogue.
// ---------------------------------------------------------------------------
__global__ void __launch_bounds__(512, 1)
gemm_stats_kernel(const float* __restrict__ temperature) {
    extern __shared__ char dsm[];
    uint32_t sbase = smem_u32(dsm);
    const int tid = threadIdx.x, warp = tid >> 5, lane = tid & 31;
    const int bi = blockIdx.y, bj = blockIdx.x;
    const int wr = warp >> 3;    // 0..1  (64-row slab)
    const int wc = warp & 7;     // 0..7  (32-col slab)
    const int grp = lane >> 2;   // 0..7
    const int qid = lane & 3;    // 0..3

    uint32_t mb_full = sbase + SM_CTRL;   // 3 barriers, 8B apart

    if (tid == 0) {
        mb_init(mb_full + 0, 1);
        mb_init(mb_full + 8, 1);
        mb_init(mb_full + 16, 1);
    }
    __syncthreads();

    const char* Abase = (const char*)g_ln + (size_t)bi * NKB * A_TILE_B;
    const char* Bbase = (const char*)g_rn + (size_t)bj * NKB * B_TILE_B;

    if (tid == 0) {
        #pragma unroll
        for (int k = 0; k < NSTAGE; ++k) {
            mb_expect(mb_full + 8 * k, STAGE_B);
            bulk_g2s(sbase + k * STAGE_B, Abase + (size_t)k * A_TILE_B,
                     A_TILE_B, mb_full + 8 * k);
            bulk_g2s(sbase + k * STAGE_B + A_TILE_B, Bbase + (size_t)k * B_TILE_B,
                     B_TILE_B, mb_full + 8 * k);
        }
    }

    float acc[4][4][4];
    #pragma unroll
    for (int mt = 0; mt < 4; ++mt)
        #pragma unroll
        for (int nt = 0; nt < 4; ++nt)
            #pragma unroll
            for (int c = 0; c < 4; ++c) acc[mt][nt][c] = 0.0f;

    // per-lane ldmatrix address components
    const int a_row_in = (lane & 7) + ((lane >> 3) & 1) * 8;  // row within 16
    const int a_koff   = ((lane >> 4) & 1) * 16;              // byte
    const int b_n_in   = (lane & 7) + ((lane >> 4) & 1) * 8;  // n within 16
    const int b_koff   = ((lane >> 3) & 1) * 16;              // byte

    for (int k = 0; k < NKB; ++k) {
        int s = k % NSTAGE;
        int p = (k / NSTAGE) & 1;
        mb_wait(mb_full + 8 * s, p);

        uint32_t sA = sbase + s * STAGE_B;
        uint32_t sB = sA + A_TILE_B;

        #pragma unroll
        for (int kk = 0; kk < 4; ++kk) {        // 4 x k16 within BK=64
            int kbA = kk * 32 + a_koff;
            int kbB = kk * 32 + b_koff;
            uint32_t af[4][4], bf[4][2];
            #pragma unroll
            for (int mt = 0; mt < 4; ++mt) {
                int row = wr * 64 + mt * 16 + a_row_in;
                ldsm_x4(af[mt][0], af[mt][1], af[mt][2], af[mt][3],
                        sA + swz_off(row, kbA));
            }
            #pragma unroll
            for (int pr = 0; pr < 2; ++pr) {
                int n = wc * 32 + pr * 16 + b_n_in;
                uint32_t r0, r1, r2, r3;
                ldsm_x4(r0, r1, r2, r3, sB + swz_off(n, kbB));
                bf[2 * pr][0] = r0;  bf[2 * pr][1] = r1;
                bf[2 * pr + 1][0] = r2;  bf[2 * pr + 1][1] = r3;
            }
            #pragma unroll
            for (int mt = 0; mt < 4; ++mt)
                #pragma unroll
                for (int nt = 0; nt < 4; ++nt)
                    mma16816(acc[mt][nt], af[mt], bf[nt]);
        }

        __syncthreads();   // stage s fully consumed by all warps
        if (tid == 0 && k + NSTAGE < NKB) {
            int kn = k + NSTAGE;
            mb_expect(mb_full + 8 * s, STAGE_B);
            bulk_g2s(sA, Abase + (size_t)kn * A_TILE_B, A_TILE_B, mb_full + 8 * s);
            bulk_g2s(sB, Bbase + (size_t)kn * B_TILE_B, B_TILE_B, mb_full + 8 * s);
        }
    }

    // ---- epilogue ----
    const float scale = __expf(temperature[0]);

    #pragma unroll
    for (int mt = 0; mt < 4; ++mt)
        #pragma unroll
        for (int nt = 0; nt < 4; ++nt)
            #pragma unroll
            for (int c = 0; c < 4; ++c)
                acc[mt][nt][c] = fast_exp(fmaf(acc[mt][nt][c], scale, -scale));

    // row sums (reduce over qid lanes, then atomics)
    #pragma unroll
    for (int mt = 0; mt < 4; ++mt) {
        float s0 = 0.0f, s1 = 0.0f;
        #pragma unroll
        for (int nt = 0; nt < 4; ++nt) {
            s0 += acc[mt][nt][0] + acc[mt][nt][1];
            s1 += acc[mt][nt][2] + acc[mt][nt][3];
        }
        s0 += __shfl_xor_sync(0xffffffffu, s0, 1);
        s0 += __shfl_xor_sync(0xffffffffu, s0, 2);
        s1 += __shfl_xor_sync(0xffffffffu, s1, 1);
        s1 += __shfl_xor_sync(0xffffffffu, s1, 2);
        if (qid == 0) {
            int row = bi * BM + wr * 64 + mt * 16 + grp;
            atomicAdd(&g_rowsum[row], s0);
            atomicAdd(&g_rowsum[row + 8], s1);
        }
    }

    // col sums (reduce over grp lanes, then atomics)
    #pragma unroll
    for (int nt = 0; nt < 4; ++nt) {
        float t0 = 0.0f, t1 = 0.0f;
        #pragma unroll
        for (int mt = 0; mt < 4; ++mt) {
            t0 += acc[mt][nt][0] + acc[mt][nt][2];
            t1 += acc[mt][nt][1] + acc[mt][nt][3];
        }
        t0 += __shfl_xor_sync(0xffffffffu, t0, 4);
        t0 += __shfl_xor_sync(0xffffffffu, t0, 8);
        t0 += __shfl_xor_sync(0xffffffffu, t0, 16);
        t1 += __shfl_xor_sync(0xffffffffu, t1, 4);
        t1 += __shfl_xor_sync(0xffffffffu, t1, 8);
        t1 += __shfl_xor_sync(0xffffffffu, t1, 16);
        if (grp == 0) {
            int col = bj * BN + wc * 32 + nt * 8 + 2 * qid;
            atomicAdd(&g_colsum[col], t0);
            atomicAdd(&g_colsum[col + 1], t1);
        }
    }

    // diagonal elements (CTA intersects diagonal when bi>>1 == bj)
    if ((bi >> 1) == bj) {
        int doff = (bi & 1) * 128;
        #pragma unroll
        for (int mt = 0; mt < 4; ++mt) {
            int lr = wr * 64 + mt * 16 + grp;
            #pragma unroll
            for (int nt = 0; nt < 4; ++nt) {
                int lc = wc * 32 + nt * 8 + 2 * qid;
                if (lc == lr + doff)         g_diag[bi * BM + lr]     = acc[mt][nt][0];
                if (lc + 1 == lr + doff)     g_diag[bi * BM + lr]     = acc[mt][nt][1];
                if (lc == lr + 8 + doff)     g_diag[bi * BM + lr + 8] = acc[mt][nt][2];
                if (lc + 1 == lr + 8 + doff) g_diag[bi * BM + lr + 8] = acc[mt][nt][3];
            }
        }
    }
}

// ---------------------------------------------------------------------------
// Kernel 3: traces -> closed-form loss
// ---------------------------------------------------------------------------
__global__ void finalize_kernel(float* __restrict__ out) {
    int tid = threadIdx.x;
    float tl = 0.0f, tr = 0.0f;
    for (int i = tid; i < B_SZ; i += 256) {
        float d = g_diag[i];
        tl += d / g_rowsum[i];
        tr += d / g_colsum[i];
    }
    #pragma unroll
    for (int o = 16; o > 0; o >>= 1) {
        tl += __shfl_xor_sync(0xffffffffu, tl, o);
        tr += __shfl_xor_sync(0xffffffffu, tr, o);
    }
    __shared__ float sl[8], sr[8];
    if ((tid & 31) == 0) { sl[tid >> 5] = tl; sr[tid >> 5] = tr; }
    __syncthreads();
    if (tid == 0) {
        float TL = 0.0f, TR = 0.0f;
        #pragma unroll
        for (int w = 0; w < 8; ++w) { TL += sl[w]; TR += sr[w]; }
        float logeps = logf(EPS_F);
        float log1m  = logf(1.0f - EPS_F);
        float ll = -(TL * log1m + ((float)B_SZ - TL) * logeps);
        float lr = -(TR * log1m + ((float)B_SZ - TR) * logeps);
        out[0] = (ll + lr) * 0.5f / (float)B_SZ;
    }
}

// ---------------------------------------------------------------------------
extern "C" void kernel_launch(void* const* d_in, const int* in_sizes, int n_in,
                              void* d_out, int out_size) {
    const float* left  = (const float*)d_in[0];
    const float* right = (const float*)d_in[1];
    const float* temp  = (const float*)d_in[2];

    static bool attr_set = false;
    if (!attr_set) {
        cudaFuncSetAttribute(gemm_stats_kernel,
                             cudaFuncAttributeMaxDynamicSharedMemorySize,
                             DSMEM_TOTAL);
        attr_set = true;
    }

    normalize_kernel<<<1024, 256>>>(left, right);
    dim3 grid(B_SZ / BN, B_SZ / BM);  // (16, 32)
    gemm_stats_kernel<<<grid, 512, DSMEM_TOTAL>>>(temp);
    finalize_kernel<<<1, 256>>>((float*)d_out);
}